// round 2
// baseline (speedup 1.0000x reference)
#include <cuda_runtime.h>
#include <math.h>

#define NN   8192
#define CHN  128
#define BBS  16
#define NSEQ 512
#define NHD  8
#define DH   16
#define NE   131072

// ---------------- scratch (device globals; no allocations allowed) ----------------
__device__ float g_xw  [NN*CHN];
__device__ float g_q   [NN*CHN];
__device__ float g_k   [NN*CHN];
__device__ float g_v   [NN*CHN];
__device__ float g_att [NN*CHN];
__device__ float g_t1  [NN*CHN];
__device__ float g_t2  [NN*CHN];
__device__ float g_ot  [NN*CHN];
__device__ float g_mlp1[NN*2*CHN];
__device__ float g_t3  [NN*CHN];
__device__ float g_biasT[(size_t)BBS*NHD*NSEQ*NSEQ];   // 134 MB transposed bias [B,H,N,N]
__device__ int   g_cnt [NN];
__device__ int   g_off [NN+1];
__device__ int   g_cur [NN];
__device__ int   g_ssrc[NE];
__device__ float g_dinv[NN];
__device__ float g_psum[128*CHN];
__device__ float g_psq [128*CHN];
__device__ float g_mean[3][CHN];
__device__ float g_rstd[3][CHN];

// ---------------- CSR build for GCN scatter ----------------
__global__ void k_zero() {
    int i = blockIdx.x*blockDim.x + threadIdx.x;
    if (i < NN) { g_cnt[i] = 0; g_cur[i] = 0; }
}

__global__ void k_hist(const int* __restrict__ ei) {
    int e = blockIdx.x*blockDim.x + threadIdx.x;
    if (e < NE) atomicAdd(&g_cnt[ei[NE + e]], 1);
}

__global__ void k_scan() {
    // 1 block, 1024 threads; exclusive scan of g_cnt[8192] -> g_off, plus dinv
    __shared__ int sm[1024];
    int t = threadIdx.x;
    int base = t*8;
    int v[8];
#pragma unroll
    for (int j = 0; j < 8; j++) v[j] = g_cnt[base+j];
    int tot = 0;
#pragma unroll
    for (int j = 0; j < 8; j++) { int tmp = v[j]; v[j] = tot; tot += tmp; }
    sm[t] = tot;
    __syncthreads();
    for (int off = 1; off < 1024; off <<= 1) {
        int val = sm[t];
        int add = (t >= off) ? sm[t-off] : 0;
        __syncthreads();
        sm[t] = val + add;
        __syncthreads();
    }
    int excl = (t == 0) ? 0 : sm[t-1];
#pragma unroll
    for (int j = 0; j < 8; j++) g_off[base+j] = excl + v[j];
    if (t == 1023) g_off[NN] = sm[1023];
#pragma unroll
    for (int j = 0; j < 8; j++)
        g_dinv[base+j] = rsqrtf(1.0f + (float)g_cnt[base+j]);
}

__global__ void k_fill(const int* __restrict__ ei) {
    int e = blockIdx.x*blockDim.x + threadIdx.x;
    if (e < NE) {
        int src = ei[e];
        int dst = ei[NE + e];
        int pos = atomicAdd(&g_cur[dst], 1);
        g_ssrc[g_off[dst] + pos] = src;
    }
}

// ---------------- GCN gather: t1 = hconv + x (hconv = segsum + conv_b) ----------------
__global__ void k_gather(const float* __restrict__ x, const float* __restrict__ conv_b) {
    int dst = blockIdx.x;
    int ch  = threadIdx.x;
    float di  = g_dinv[dst];
    float acc = g_xw[dst*CHN + ch] * di;          // self loop
    int s0 = g_off[dst], s1 = g_off[dst+1];
    for (int i = s0; i < s1; i++) {
        int s = g_ssrc[i];
        acc += g_xw[s*CHN + ch] * g_dinv[s];
    }
    g_t1[dst*CHN + ch] = acc*di + conv_b[ch] + x[dst*CHN + ch];
}

// ---------------- generic fp32 GEMM: out = alpha*(A@W + bias) [relu] [+resid] ----------------
template<int K, int N, bool RELU>
__global__ __launch_bounds__(256) void k_gemm(const float* __restrict__ A,
                                              const float* __restrict__ W,
                                              const float* __restrict__ bias,
                                              const float* __restrict__ resid,
                                              float alpha,
                                              float* __restrict__ out) {
    __shared__ float As[16][64];
    __shared__ float Bs[16][64];
    const int bm = blockIdx.y;
    const int bn = blockIdx.x;
    const int tid = threadIdx.x;
    const int tx = tid & 15, ty = tid >> 4;

    const int ar = tid >> 2;
    const int ac = (tid & 3) << 2;
    const int br = tid >> 4;
    const int bc = (tid & 15) << 2;

    const float* Ap = A + (size_t)(bm*64 + ar)*K + ac;
    const float* Wp = W + (size_t)br*N + bn*64 + bc;

    float acc[4][4];
#pragma unroll
    for (int i = 0; i < 4; i++)
#pragma unroll
        for (int j = 0; j < 4; j++) acc[i][j] = 0.f;

    for (int k0 = 0; k0 < K; k0 += 16) {
        float4 av = *(const float4*)(Ap + k0);
        float4 bv = *(const float4*)(Wp + (size_t)k0*N);
        As[ac+0][ar] = av.x; As[ac+1][ar] = av.y;
        As[ac+2][ar] = av.z; As[ac+3][ar] = av.w;
        *(float4*)&Bs[br][bc] = bv;
        __syncthreads();
#pragma unroll
        for (int kk = 0; kk < 16; kk++) {
            float a[4], b[4];
            *(float4*)a = *(const float4*)&As[kk][ty*4];
            *(float4*)b = *(const float4*)&Bs[kk][tx*4];
#pragma unroll
            for (int i = 0; i < 4; i++)
#pragma unroll
                for (int j = 0; j < 4; j++)
                    acc[i][j] = fmaf(a[i], b[j], acc[i][j]);
        }
        __syncthreads();
    }

    float bb[4] = {0.f, 0.f, 0.f, 0.f};
    if (bias) *(float4*)bb = *(const float4*)&bias[bn*64 + tx*4];
#pragma unroll
    for (int i = 0; i < 4; i++) {
        int row = bm*64 + ty*4 + i;
        float4 r = make_float4(0.f, 0.f, 0.f, 0.f);
        if (resid) r = *(const float4*)&resid[(size_t)row*N + bn*64 + tx*4];
        float4 c;
        c.x = alpha*(acc[i][0] + bb[0]);
        c.y = alpha*(acc[i][1] + bb[1]);
        c.z = alpha*(acc[i][2] + bb[2]);
        c.w = alpha*(acc[i][3] + bb[3]);
        if (RELU) { c.x = fmaxf(c.x,0.f); c.y = fmaxf(c.y,0.f); c.z = fmaxf(c.z,0.f); c.w = fmaxf(c.w,0.f); }
        c.x += r.x; c.y += r.y; c.z += r.z; c.w += r.w;
        *(float4*)&out[(size_t)row*N + bn*64 + tx*4] = c;
    }
}

// ---------------- bias transpose: [B,N,N,H] -> [B,H,N,N] ----------------
__global__ void k_biasT(const float* __restrict__ bias) {
    __shared__ float sm[8][516];
    int q = blockIdx.x;
    int b = blockIdx.y;
    const float4* src = (const float4*)(bias + (size_t)(b*NSEQ + q)*NSEQ*NHD);
    for (int i4 = threadIdx.x; i4 < NSEQ*NHD/4; i4 += 128) {
        float4 v = src[i4];
        int k  = i4 >> 1;
        int h0 = (i4 & 1) << 2;
        sm[h0+0][k] = v.x; sm[h0+1][k] = v.y; sm[h0+2][k] = v.z; sm[h0+3][k] = v.w;
    }
    __syncthreads();
    for (int i = threadIdx.x; i < NSEQ*NHD; i += 128) {
        int h = i >> 9;
        int k = i & 511;
        g_biasT[((size_t)(b*NHD + h)*NSEQ + q)*NSEQ + k] = sm[h][k];
    }
}

// ---------------- fused attention: per (b,h, 64-row q tile) ----------------
__global__ __launch_bounds__(256, 2) void k_attn() {
    extern __shared__ float smem[];
    float (*Ks)[20] = (float(*)[20])smem;
    float (*Vs)[20] = (float(*)[20])(smem + 512*20);
    float (*Qs)[20] = (float(*)[20])(smem + 1024*20);

    const int bh = blockIdx.y;
    const int b  = bh >> 3;
    const int h  = bh & 7;
    const int q0 = blockIdx.x * 64;
    const int tid = threadIdx.x;

    for (int idx = tid; idx < 512*4; idx += 256) {
        int kk = idx >> 2;
        int d4 = (idx & 3) << 2;
        size_t g = (size_t)(b*NSEQ + kk)*CHN + h*DH + d4;
        *(float4*)&Ks[kk][d4] = *(const float4*)&g_k[g];
        *(float4*)&Vs[kk][d4] = *(const float4*)&g_v[g];
    }
    for (int idx = tid; idx < 64*4; idx += 256) {
        int r  = idx >> 2;
        int d4 = (idx & 3) << 2;
        *(float4*)&Qs[r][d4] = *(const float4*)&g_q[(size_t)(b*NSEQ + q0 + r)*CHN + h*DH + d4];
    }
    __syncthreads();

    const int wid = tid >> 5, lane = tid & 31;

    for (int i = 0; i < 8; i++) {
        int rql = wid*8 + i;
        int row = q0 + rql;
        float qv[16];
        *(float4*)&qv[0]  = *(const float4*)&Qs[rql][0];
        *(float4*)&qv[4]  = *(const float4*)&Qs[rql][4];
        *(float4*)&qv[8]  = *(const float4*)&Qs[rql][8];
        *(float4*)&qv[12] = *(const float4*)&Qs[rql][12];

        const float* brow = g_biasT + ((size_t)bh*NSEQ + row)*NSEQ;

        float p[16];
        float m = -1e30f;
#pragma unroll
        for (int j = 0; j < 16; j++) {
            int kk = j*32 + lane;
            float4 k0 = *(const float4*)&Ks[kk][0];
            float4 k1 = *(const float4*)&Ks[kk][4];
            float4 k2 = *(const float4*)&Ks[kk][8];
            float4 k3 = *(const float4*)&Ks[kk][12];
            float acc = qv[0]*k0.x;
            acc = fmaf(qv[1],  k0.y, acc); acc = fmaf(qv[2],  k0.z, acc); acc = fmaf(qv[3],  k0.w, acc);
            acc = fmaf(qv[4],  k1.x, acc); acc = fmaf(qv[5],  k1.y, acc); acc = fmaf(qv[6],  k1.z, acc);
            acc = fmaf(qv[7],  k1.w, acc); acc = fmaf(qv[8],  k2.x, acc); acc = fmaf(qv[9],  k2.y, acc);
            acc = fmaf(qv[10], k2.z, acc); acc = fmaf(qv[11], k2.w, acc); acc = fmaf(qv[12], k3.x, acc);
            acc = fmaf(qv[13], k3.y, acc); acc = fmaf(qv[14], k3.z, acc); acc = fmaf(qv[15], k3.w, acc);
            acc += brow[kk];
            p[j] = acc;
            m = fmaxf(m, acc);
        }
#pragma unroll
        for (int off = 16; off > 0; off >>= 1)
            m = fmaxf(m, __shfl_xor_sync(0xffffffffu, m, off));
        float sum = 0.f;
#pragma unroll
        for (int j = 0; j < 16; j++) { p[j] = __expf(p[j] - m); sum += p[j]; }
#pragma unroll
        for (int off = 16; off > 0; off >>= 1)
            sum += __shfl_xor_sync(0xffffffffu, sum, off);
        float inv = 1.0f / sum;

        float o[16];
#pragma unroll
        for (int d = 0; d < 16; d++) o[d] = 0.f;
#pragma unroll
        for (int j = 0; j < 16; j++) {
            int kk = j*32 + lane;
            float pj = p[j];
            float4 v0 = *(const float4*)&Vs[kk][0];
            float4 v1 = *(const float4*)&Vs[kk][4];
            float4 v2 = *(const float4*)&Vs[kk][8];
            float4 v3 = *(const float4*)&Vs[kk][12];
            o[0]  = fmaf(pj, v0.x, o[0]);  o[1]  = fmaf(pj, v0.y, o[1]);
            o[2]  = fmaf(pj, v0.z, o[2]);  o[3]  = fmaf(pj, v0.w, o[3]);
            o[4]  = fmaf(pj, v1.x, o[4]);  o[5]  = fmaf(pj, v1.y, o[5]);
            o[6]  = fmaf(pj, v1.z, o[6]);  o[7]  = fmaf(pj, v1.w, o[7]);
            o[8]  = fmaf(pj, v2.x, o[8]);  o[9]  = fmaf(pj, v2.y, o[9]);
            o[10] = fmaf(pj, v2.z, o[10]); o[11] = fmaf(pj, v2.w, o[11]);
            o[12] = fmaf(pj, v3.x, o[12]); o[13] = fmaf(pj, v3.y, o[13]);
            o[14] = fmaf(pj, v3.z, o[14]); o[15] = fmaf(pj, v3.w, o[15]);
        }
#pragma unroll
        for (int d = 0; d < 16; d++) {
#pragma unroll
            for (int off = 16; off > 0; off >>= 1)
                o[d] += __shfl_xor_sync(0xffffffffu, o[d], off);
        }
        if (lane < 16) {
            float val = o[0];
#pragma unroll
            for (int d = 1; d < 16; d++)
                if (lane == d) val = o[d];
            g_att[(size_t)(b*NSEQ + row)*CHN + h*DH + lane] = val * inv;
        }
    }
}

// ---------------- BatchNorm stats (two stage, deterministic) ----------------
__global__ void k_stats(const float* __restrict__ in) {
    int ch = threadIdx.x;
    int cb = blockIdx.x;
    float s = 0.f, q = 0.f;
    for (int r = cb*64; r < cb*64 + 64; r++) {
        float v = in[(size_t)r*CHN + ch];
        s += v; q = fmaf(v, v, q);
    }
    g_psum[cb*CHN + ch] = s;
    g_psq [cb*CHN + ch] = q;
}

__global__ void k_stats_fin(int idx) {
    int ch = threadIdx.x;
    float s = 0.f, q = 0.f;
    for (int i = 0; i < 128; i++) { s += g_psum[i*CHN + ch]; q += g_psq[i*CHN + ch]; }
    float mean = s * (1.0f/NN);
    float var  = q * (1.0f/NN) - mean*mean;
    g_mean[idx][ch] = mean;
    g_rstd[idx][ch] = rsqrtf(var + 1e-5f);
}

__global__ void k_combine(const float* __restrict__ g1, const float* __restrict__ be1,
                          const float* __restrict__ g2, const float* __restrict__ be2) {
    int i = blockIdx.x*blockDim.x + threadIdx.x;
    int ch = i & (CHN-1);
    float a = (g_t1[i] - g_mean[0][ch]) * g_rstd[0][ch] * g1[ch] + be1[ch];
    float b = (g_t2[i] - g_mean[1][ch]) * g_rstd[1][ch] * g2[ch] + be2[ch];
    g_ot[i] = a + b;
}

__global__ void k_final(const float* __restrict__ g3, const float* __restrict__ be3,
                        float* __restrict__ out) {
    int i = blockIdx.x*blockDim.x + threadIdx.x;
    int ch = i & (CHN-1);
    out[i] = (g_t3[i] - g_mean[2][ch]) * g_rstd[2][ch] * g3[ch] + be3[ch];
}

// ---------------- launch ----------------
extern "C" void kernel_launch(void* const* d_in, const int* in_sizes, int n_in,
                              void* d_out, int out_size) {
    const float* x      = (const float*)d_in[0];
    const int*   ei     = (const int*)  d_in[1];
    const float* abias  = (const float*)d_in[3];
    const float* conv_w = (const float*)d_in[4];
    const float* conv_b = (const float*)d_in[5];
    const float* wq = (const float*)d_in[6];  const float* bq = (const float*)d_in[7];
    const float* wk = (const float*)d_in[8];  const float* bk = (const float*)d_in[9];
    const float* wv = (const float*)d_in[10]; const float* bv = (const float*)d_in[11];
    const float* wo = (const float*)d_in[12]; const float* bo = (const float*)d_in[13];
    const float* w1 = (const float*)d_in[14]; const float* b1 = (const float*)d_in[15];
    const float* w2 = (const float*)d_in[16]; const float* b2 = (const float*)d_in[17];
    const float* g1 = (const float*)d_in[18]; const float* be1 = (const float*)d_in[19];
    const float* g2 = (const float*)d_in[20]; const float* be2 = (const float*)d_in[21];
    const float* g3 = (const float*)d_in[22]; const float* be3 = (const float*)d_in[23];
    float* out = (float*)d_out;

    // --- resolve device-symbol addresses (host code must NOT use symbols as args) ---
    float *p_xw, *p_q, *p_k, *p_v, *p_att, *p_t2, *p_ot, *p_mlp1, *p_t3;
    cudaGetSymbolAddress((void**)&p_xw,   g_xw);
    cudaGetSymbolAddress((void**)&p_q,    g_q);
    cudaGetSymbolAddress((void**)&p_k,    g_k);
    cudaGetSymbolAddress((void**)&p_v,    g_v);
    cudaGetSymbolAddress((void**)&p_att,  g_att);
    cudaGetSymbolAddress((void**)&p_t2,   g_t2);
    cudaGetSymbolAddress((void**)&p_ot,   g_ot);
    cudaGetSymbolAddress((void**)&p_mlp1, g_mlp1);
    cudaGetSymbolAddress((void**)&p_t3,   g_t3);
    float *p_t1; cudaGetSymbolAddress((void**)&p_t1, g_t1);

    const int ATTN_SMEM = (512 + 512 + 64) * 20 * (int)sizeof(float);
    cudaFuncSetAttribute(k_attn, cudaFuncAttributeMaxDynamicSharedMemorySize, ATTN_SMEM);

    // CSR build
    k_zero<<<32, 256>>>();
    k_hist<<<NE/256, 256>>>(ei);
    k_scan<<<1, 1024>>>();
    k_fill<<<NE/256, 256>>>(ei);

    // projections
    k_gemm<128,128,false><<<dim3(2,128), 256>>>(x, conv_w, nullptr, nullptr, 1.0f, p_xw);
    k_gemm<128,128,false><<<dim3(2,128), 256>>>(x, wq, bq, nullptr, 0.25f, p_q);
    k_gemm<128,128,false><<<dim3(2,128), 256>>>(x, wk, bk, nullptr, 1.0f, p_k);
    k_gemm<128,128,false><<<dim3(2,128), 256>>>(x, wv, bv, nullptr, 1.0f, p_v);

    // bias transpose + GCN gather
    k_biasT<<<dim3(512,16), 128>>>(abias);
    k_gather<<<NN, 128>>>(x, conv_b);

    // attention
    k_attn<<<dim3(8,128), 256, ATTN_SMEM>>>();
    k_gemm<128,128,false><<<dim3(2,128), 256>>>(p_att, wo, bo, x, 1.0f, p_t2);

    // BN1, BN2 then combine
    k_stats<<<128,128>>>(p_t1);  k_stats_fin<<<1,128>>>(0);
    k_stats<<<128,128>>>(p_t2);  k_stats_fin<<<1,128>>>(1);
    k_combine<<<NN*CHN/256, 256>>>(g1, be1, g2, be2);

    // MLP with residual
    k_gemm<128,256,true ><<<dim3(4,128), 256>>>(p_ot,  w1, b1, nullptr, 1.0f, p_mlp1);
    k_gemm<256,128,false><<<dim3(2,128), 256>>>(p_mlp1, w2, b2, p_ot,   1.0f, p_t3);

    // BN3 -> output
    k_stats<<<128,128>>>(p_t3);  k_stats_fin<<<1,128>>>(2);
    k_final<<<NN*CHN/256, 256>>>(g3, be3, out);
}

// round 3
// speedup vs baseline: 1.3818x; 1.3818x over previous
#include <cuda_runtime.h>
#include <math.h>

#define NN   8192
#define CHN  128
#define BBS  16
#define NSEQ 512
#define NHD  8
#define DH   16
#define NE   131072

// ---------------- scratch (device globals; no allocations allowed) ----------------
__device__ float g_qkvc[NN*512];          // [xw | q*scale | k | v]
__device__ float g_att [NN*CHN];
__device__ float g_t1  [NN*CHN];
__device__ float g_t2  [NN*CHN];
__device__ float g_ot  [NN*CHN];
__device__ float g_mlp1[NN*2*CHN];
__device__ float g_t3  [NN*CHN];
__device__ float g_Wp  [CHN*512];
__device__ float g_Bp  [512];
__device__ int   g_cnt [NN];
__device__ int   g_off [NN+1];
__device__ int   g_cur [NN];
__device__ int   g_ssrc[NE];
__device__ float g_dinv[NN];
__device__ float g_psum [128*CHN];
__device__ float g_psq  [128*CHN];
__device__ float g_psum2[128*CHN];
__device__ float g_psq2 [128*CHN];
__device__ float g_mean[3][CHN];
__device__ float g_rstd[3][CHN];

// ---------------- CSR build ----------------
__global__ void k_zero() {
    int i = blockIdx.x*blockDim.x + threadIdx.x;
    if (i < NN) { g_cnt[i] = 0; g_cur[i] = 0; }
}
__global__ void k_hist(const int* __restrict__ ei) {
    int e = blockIdx.x*blockDim.x + threadIdx.x;
    if (e < NE) atomicAdd(&g_cnt[ei[NE + e]], 1);
}
__global__ void k_scan() {
    __shared__ int sm[1024];
    int t = threadIdx.x;
    int base = t*8;
    int v[8];
#pragma unroll
    for (int j = 0; j < 8; j++) v[j] = g_cnt[base+j];
    int tot = 0;
#pragma unroll
    for (int j = 0; j < 8; j++) { int tmp = v[j]; v[j] = tot; tot += tmp; }
    sm[t] = tot;
    __syncthreads();
    for (int off = 1; off < 1024; off <<= 1) {
        int val = sm[t];
        int add = (t >= off) ? sm[t-off] : 0;
        __syncthreads();
        sm[t] = val + add;
        __syncthreads();
    }
    int excl = (t == 0) ? 0 : sm[t-1];
#pragma unroll
    for (int j = 0; j < 8; j++) g_off[base+j] = excl + v[j];
    if (t == 1023) g_off[NN] = sm[1023];
#pragma unroll
    for (int j = 0; j < 8; j++)
        g_dinv[base+j] = rsqrtf(1.0f + (float)g_cnt[base+j]);
}
__global__ void k_fill(const int* __restrict__ ei) {
    int e = blockIdx.x*blockDim.x + threadIdx.x;
    if (e < NE) {
        int src = ei[e];
        int dst = ei[NE + e];
        int pos = atomicAdd(&g_cur[dst], 1);
        g_ssrc[g_off[dst] + pos] = src;
    }
}

// ---------------- weight pack: [conv | wq*0.25 | wk | wv], bias likewise ----------------
__global__ void k_pack(const float* __restrict__ cw,
                       const float* __restrict__ wq, const float* __restrict__ bq,
                       const float* __restrict__ wk, const float* __restrict__ bk,
                       const float* __restrict__ wv, const float* __restrict__ bv) {
    int i = blockIdx.x*blockDim.x + threadIdx.x;   // 128*512
    int r = i >> 9, c = i & 511;
    float v;
    if      (c < 128) v = cw[r*128 + c];
    else if (c < 256) v = wq[r*128 + (c-128)] * 0.25f;
    else if (c < 384) v = wk[r*128 + (c-256)];
    else              v = wv[r*128 + (c-384)];
    g_Wp[i] = v;
    if (r == 0) {
        float b = 0.f;
        if      (c >= 384) b = bv[c-384];
        else if (c >= 256) b = bk[c-256];
        else if (c >= 128) b = bq[c-128]*0.25f;
        g_Bp[c] = b;
    }
}

// ---------------- GCN gather: t1 = segsum + conv_b + x ----------------
__global__ void k_gather(const float* __restrict__ x, const float* __restrict__ conv_b) {
    int dst = blockIdx.x;
    int ch  = threadIdx.x;
    float di  = g_dinv[dst];
    float acc = g_qkvc[(size_t)dst*512 + ch] * di;     // self loop
    int s0 = g_off[dst], s1 = g_off[dst+1];
    for (int i = s0; i < s1; i++) {
        int s = g_ssrc[i];
        acc += g_qkvc[(size_t)s*512 + ch] * g_dinv[s];
    }
    g_t1[dst*CHN + ch] = acc*di + conv_b[ch] + x[dst*CHN + ch];
}

// ---------------- generic fp32 GEMM ----------------
template<int K, int N, bool RELU>
__global__ __launch_bounds__(256) void k_gemm(const float* __restrict__ A,
                                              const float* __restrict__ W,
                                              const float* __restrict__ bias,
                                              const float* __restrict__ resid,
                                              float* __restrict__ out) {
    __shared__ float As[16][64];
    __shared__ float Bs[16][64];
    const int bm = blockIdx.y;
    const int bn = blockIdx.x;
    const int tid = threadIdx.x;
    const int tx = tid & 15, ty = tid >> 4;

    const int ar = tid >> 2;
    const int ac = (tid & 3) << 2;
    const int br = tid >> 4;
    const int bc = (tid & 15) << 2;

    const float* Ap = A + (size_t)(bm*64 + ar)*K + ac;
    const float* Wp = W + (size_t)br*N + bn*64 + bc;

    float acc[4][4];
#pragma unroll
    for (int i = 0; i < 4; i++)
#pragma unroll
        for (int j = 0; j < 4; j++) acc[i][j] = 0.f;

    for (int k0 = 0; k0 < K; k0 += 16) {
        float4 av = *(const float4*)(Ap + k0);
        float4 bv = *(const float4*)(Wp + (size_t)k0*N);
        As[ac+0][ar] = av.x; As[ac+1][ar] = av.y;
        As[ac+2][ar] = av.z; As[ac+3][ar] = av.w;
        *(float4*)&Bs[br][bc] = bv;
        __syncthreads();
#pragma unroll
        for (int kk = 0; kk < 16; kk++) {
            float a[4], b[4];
            *(float4*)a = *(const float4*)&As[kk][ty*4];
            *(float4*)b = *(const float4*)&Bs[kk][tx*4];
#pragma unroll
            for (int i = 0; i < 4; i++)
#pragma unroll
                for (int j = 0; j < 4; j++)
                    acc[i][j] = fmaf(a[i], b[j], acc[i][j]);
        }
        __syncthreads();
    }

    float bb[4] = {0.f, 0.f, 0.f, 0.f};
    if (bias) *(float4*)bb = *(const float4*)&bias[bn*64 + tx*4];
#pragma unroll
    for (int i = 0; i < 4; i++) {
        int row = bm*64 + ty*4 + i;
        float4 r = make_float4(0.f, 0.f, 0.f, 0.f);
        if (resid) r = *(const float4*)&resid[(size_t)row*N + bn*64 + tx*4];
        float4 c;
        c.x = acc[i][0] + bb[0];
        c.y = acc[i][1] + bb[1];
        c.z = acc[i][2] + bb[2];
        c.w = acc[i][3] + bb[3];
        if (RELU) { c.x = fmaxf(c.x,0.f); c.y = fmaxf(c.y,0.f); c.z = fmaxf(c.z,0.f); c.w = fmaxf(c.w,0.f); }
        c.x += r.x; c.y += r.y; c.z += r.z; c.w += r.w;
        *(float4*)&out[(size_t)row*N + bn*64 + tx*4] = c;
    }
}

// ---------------- fused all-head attention, direct bias read ----------------
// block = (q-tile of 64, b). 512 threads: thread owns (q = t>>3, h = t&7).
// smem: per-head padded K,V tiles of 64 k-rows: base_h = h*1028 floats.
#define HPAD 1028
__global__ __launch_bounds__(512) void k_attn(const float* __restrict__ bias) {
    extern __shared__ float sm[];
    float* Ks = sm;                 // 8*1028 floats
    float* Vs = sm + NHD*HPAD;      // 8*1028 floats

    const int b  = blockIdx.y;
    const int q0 = blockIdx.x * 64;
    const int t  = threadIdx.x;
    const int h  = t & 7;
    const int ql = t >> 3;              // 0..63
    const int q  = q0 + ql;

    // loader mapping: row kk = t>>3, head i = t&7 (each thread: 4 float4 of its seg)
    const int lkk = t >> 3;
    const int li  = t & 7;

    // Q into regs
    float qv[16];
    {
        const float4* qp = (const float4*)&g_qkvc[(size_t)(b*NSEQ + q)*512 + 128 + h*DH];
        float4 a = qp[0], b4 = qp[1], c4 = qp[2], d4 = qp[3];
        qv[0]=a.x; qv[1]=a.y; qv[2]=a.z; qv[3]=a.w;
        qv[4]=b4.x; qv[5]=b4.y; qv[6]=b4.z; qv[7]=b4.w;
        qv[8]=c4.x; qv[9]=c4.y; qv[10]=c4.z; qv[11]=c4.w;
        qv[12]=d4.x; qv[13]=d4.y; qv[14]=d4.z; qv[15]=d4.w;
    }

    const float* brow = bias + (size_t)(b*NSEQ + q)*NSEQ*NHD + h;

    float m = -1e30f, ssum = 0.f;
    float o[16];
#pragma unroll
    for (int d = 0; d < 16; d++) o[d] = 0.f;

    for (int t0 = 0; t0 < NSEQ; t0 += 64) {
        // cooperative load of K/V tile (64 rows x 128 ch)
        {
            const float4* gk = (const float4*)&g_qkvc[(size_t)(b*NSEQ + t0 + lkk)*512 + 256 + li*DH];
            const float4* gv = (const float4*)&g_qkvc[(size_t)(b*NSEQ + t0 + lkk)*512 + 384 + li*DH];
            float4* dk = (float4*)&Ks[li*HPAD + lkk*DH];
            float4* dv = (float4*)&Vs[li*HPAD + lkk*DH];
#pragma unroll
            for (int j = 0; j < 4; j++) { dk[j] = gk[j]; dv[j] = gv[j]; }
        }
        __syncthreads();

        for (int c = 0; c < 4; c++) {          // 4 chunks of 16 k
            const int kb = c*16;
            float s[16];
#pragma unroll
            for (int j = 0; j < 16; j++)
                s[j] = __ldg(brow + (size_t)(t0 + kb + j)*NHD);
#pragma unroll
            for (int j = 0; j < 16; j++) {
                const float4* kp = (const float4*)&Ks[h*HPAD + (kb + j)*DH];
                float4 k0 = kp[0], k1 = kp[1], k2 = kp[2], k3 = kp[3];
                float acc = s[j];
                acc = fmaf(qv[0],  k0.x, acc); acc = fmaf(qv[1],  k0.y, acc);
                acc = fmaf(qv[2],  k0.z, acc); acc = fmaf(qv[3],  k0.w, acc);
                acc = fmaf(qv[4],  k1.x, acc); acc = fmaf(qv[5],  k1.y, acc);
                acc = fmaf(qv[6],  k1.z, acc); acc = fmaf(qv[7],  k1.w, acc);
                acc = fmaf(qv[8],  k2.x, acc); acc = fmaf(qv[9],  k2.y, acc);
                acc = fmaf(qv[10], k2.z, acc); acc = fmaf(qv[11], k2.w, acc);
                acc = fmaf(qv[12], k3.x, acc); acc = fmaf(qv[13], k3.y, acc);
                acc = fmaf(qv[14], k3.z, acc); acc = fmaf(qv[15], k3.w, acc);
                s[j] = acc;
            }
            float lm = s[0];
#pragma unroll
            for (int j = 1; j < 16; j++) lm = fmaxf(lm, s[j]);
            float newm = fmaxf(m, lm);
            float scale = __expf(m - newm);
            ssum *= scale;
#pragma unroll
            for (int d = 0; d < 16; d++) o[d] *= scale;
#pragma unroll
            for (int j = 0; j < 16; j++) {
                float p = __expf(s[j] - newm);
                ssum += p;
                const float4* vp = (const float4*)&Vs[h*HPAD + (kb + j)*DH];
                float4 v0 = vp[0], v1 = vp[1], v2 = vp[2], v3 = vp[3];
                o[0]  = fmaf(p, v0.x, o[0]);  o[1]  = fmaf(p, v0.y, o[1]);
                o[2]  = fmaf(p, v0.z, o[2]);  o[3]  = fmaf(p, v0.w, o[3]);
                o[4]  = fmaf(p, v1.x, o[4]);  o[5]  = fmaf(p, v1.y, o[5]);
                o[6]  = fmaf(p, v1.z, o[6]);  o[7]  = fmaf(p, v1.w, o[7]);
                o[8]  = fmaf(p, v2.x, o[8]);  o[9]  = fmaf(p, v2.y, o[9]);
                o[10] = fmaf(p, v2.z, o[10]); o[11] = fmaf(p, v2.w, o[11]);
                o[12] = fmaf(p, v3.x, o[12]); o[13] = fmaf(p, v3.y, o[13]);
                o[14] = fmaf(p, v3.z, o[14]); o[15] = fmaf(p, v3.w, o[15]);
            }
            m = newm;
        }
        __syncthreads();
    }

    float inv = 1.0f / ssum;
    float4* op = (float4*)&g_att[(size_t)(b*NSEQ + q)*CHN + h*DH];
    op[0] = make_float4(o[0]*inv,  o[1]*inv,  o[2]*inv,  o[3]*inv);
    op[1] = make_float4(o[4]*inv,  o[5]*inv,  o[6]*inv,  o[7]*inv);
    op[2] = make_float4(o[8]*inv,  o[9]*inv,  o[10]*inv, o[11]*inv);
    op[3] = make_float4(o[12]*inv, o[13]*inv, o[14]*inv, o[15]*inv);
}

// ---------------- BatchNorm stats ----------------
__global__ void k_stats2(const float* __restrict__ a, const float* __restrict__ b) {
    int ch = threadIdx.x;
    int cb = blockIdx.x;
    float s1 = 0.f, q1 = 0.f, s2 = 0.f, q2 = 0.f;
    for (int r = cb*64; r < cb*64 + 64; r++) {
        float v = a[(size_t)r*CHN + ch];
        s1 += v; q1 = fmaf(v, v, q1);
        float w = b[(size_t)r*CHN + ch];
        s2 += w; q2 = fmaf(w, w, q2);
    }
    g_psum [cb*CHN + ch] = s1;  g_psq [cb*CHN + ch] = q1;
    g_psum2[cb*CHN + ch] = s2;  g_psq2[cb*CHN + ch] = q2;
}
__global__ void k_stats_fin2() {
    int ch = threadIdx.x;
    float s1=0.f,q1=0.f,s2=0.f,q2=0.f;
    for (int i = 0; i < 128; i++) {
        s1 += g_psum [i*CHN + ch]; q1 += g_psq [i*CHN + ch];
        s2 += g_psum2[i*CHN + ch]; q2 += g_psq2[i*CHN + ch];
    }
    float m1 = s1*(1.0f/NN), m2 = s2*(1.0f/NN);
    g_mean[0][ch] = m1; g_rstd[0][ch] = rsqrtf(q1*(1.0f/NN) - m1*m1 + 1e-5f);
    g_mean[1][ch] = m2; g_rstd[1][ch] = rsqrtf(q2*(1.0f/NN) - m2*m2 + 1e-5f);
}
__global__ void k_stats(const float* __restrict__ in) {
    int ch = threadIdx.x;
    int cb = blockIdx.x;
    float s = 0.f, q = 0.f;
    for (int r = cb*64; r < cb*64 + 64; r++) {
        float v = in[(size_t)r*CHN + ch];
        s += v; q = fmaf(v, v, q);
    }
    g_psum[cb*CHN + ch] = s;
    g_psq [cb*CHN + ch] = q;
}
__global__ void k_stats_fin(int idx) {
    int ch = threadIdx.x;
    float s = 0.f, q = 0.f;
    for (int i = 0; i < 128; i++) { s += g_psum[i*CHN + ch]; q += g_psq[i*CHN + ch]; }
    float mean = s * (1.0f/NN);
    float var  = q * (1.0f/NN) - mean*mean;
    g_mean[idx][ch] = mean;
    g_rstd[idx][ch] = rsqrtf(var + 1e-5f);
}

__global__ void k_combine(const float* __restrict__ g1, const float* __restrict__ be1,
                          const float* __restrict__ g2, const float* __restrict__ be2) {
    int i = blockIdx.x*blockDim.x + threadIdx.x;
    int ch = i & (CHN-1);
    float a = (g_t1[i] - g_mean[0][ch]) * g_rstd[0][ch] * g1[ch] + be1[ch];
    float b = (g_t2[i] - g_mean[1][ch]) * g_rstd[1][ch] * g2[ch] + be2[ch];
    g_ot[i] = a + b;
}
__global__ void k_final(const float* __restrict__ g3, const float* __restrict__ be3,
                        float* __restrict__ out) {
    int i = blockIdx.x*blockDim.x + threadIdx.x;
    int ch = i & (CHN-1);
    out[i] = (g_t3[i] - g_mean[2][ch]) * g_rstd[2][ch] * g3[ch] + be3[ch];
}

// ---------------- launch ----------------
extern "C" void kernel_launch(void* const* d_in, const int* in_sizes, int n_in,
                              void* d_out, int out_size) {
    const float* x      = (const float*)d_in[0];
    const int*   ei     = (const int*)  d_in[1];
    const float* abias  = (const float*)d_in[3];
    const float* conv_w = (const float*)d_in[4];
    const float* conv_b = (const float*)d_in[5];
    const float* wq = (const float*)d_in[6];  const float* bq = (const float*)d_in[7];
    const float* wk = (const float*)d_in[8];  const float* bk = (const float*)d_in[9];
    const float* wv = (const float*)d_in[10]; const float* bv = (const float*)d_in[11];
    const float* wo = (const float*)d_in[12]; const float* bo = (const float*)d_in[13];
    const float* w1 = (const float*)d_in[14]; const float* b1 = (const float*)d_in[15];
    const float* w2 = (const float*)d_in[16]; const float* b2 = (const float*)d_in[17];
    const float* g1 = (const float*)d_in[18]; const float* be1 = (const float*)d_in[19];
    const float* g2 = (const float*)d_in[20]; const float* be2 = (const float*)d_in[21];
    const float* g3 = (const float*)d_in[22]; const float* be3 = (const float*)d_in[23];
    float* out = (float*)d_out;

    float *p_qkvc, *p_att, *p_t1, *p_t2, *p_ot, *p_mlp1, *p_t3, *p_Wp, *p_Bp;
    cudaGetSymbolAddress((void**)&p_qkvc, g_qkvc);
    cudaGetSymbolAddress((void**)&p_att,  g_att);
    cudaGetSymbolAddress((void**)&p_t1,   g_t1);
    cudaGetSymbolAddress((void**)&p_t2,   g_t2);
    cudaGetSymbolAddress((void**)&p_ot,   g_ot);
    cudaGetSymbolAddress((void**)&p_mlp1, g_mlp1);
    cudaGetSymbolAddress((void**)&p_t3,   g_t3);
    cudaGetSymbolAddress((void**)&p_Wp,   g_Wp);
    cudaGetSymbolAddress((void**)&p_Bp,   g_Bp);

    const int ATTN_SMEM = 2 * NHD * HPAD * (int)sizeof(float);   // 65,792 B
    cudaFuncSetAttribute(k_attn, cudaFuncAttributeMaxDynamicSharedMemorySize, ATTN_SMEM);

    // CSR build
    k_zero<<<32, 256>>>();
    k_hist<<<NE/256, 256>>>(ei);
    k_scan<<<1, 1024>>>();
    k_fill<<<NE/256, 256>>>(ei);

    // pack weights, fused conv/Q/K/V projection
    k_pack<<<CHN*512/256, 256>>>(conv_w, wq, bq, wk, bk, wv, bv);
    k_gemm<128,512,false><<<dim3(8,128), 256>>>(x, p_Wp, p_Bp, nullptr, p_qkvc);

    // GCN gather
    k_gather<<<NN, 128>>>(x, conv_b);

    // attention (direct bias read, all heads per block)
    k_attn<<<dim3(NSEQ/64, BBS), 512, ATTN_SMEM>>>(abias);
    k_gemm<128,128,false><<<dim3(2,128), 256>>>(p_att, wo, bo, x, p_t2);

    // BN1+BN2, combine
    k_stats2<<<128,128>>>(p_t1, p_t2);
    k_stats_fin2<<<1,128>>>();
    k_combine<<<NN*CHN/256, 256>>>(g1, be1, g2, be2);

    // MLP with residual
    k_gemm<128,256,true ><<<dim3(4,128), 256>>>(p_ot,   w1, b1, nullptr, p_mlp1);
    k_gemm<256,128,false><<<dim3(2,128), 256>>>(p_mlp1, w2, b2, p_ot,    p_t3);

    // BN3 -> output
    k_stats<<<128,128>>>(p_t3);
    k_stats_fin<<<1,128>>>(2);
    k_final<<<NN*CHN/256, 256>>>(g3, be3, out);
}